// round 6
// baseline (speedup 1.0000x reference)
#include <cuda_runtime.h>
#include <cuda_bf16.h>
#include <math.h>

#define MAXN 50000
#define MAXE 600000
#define HID 128
#define NGRAPH 64

// ---------------- scratch (static device globals) ----------------
__device__ __nv_bfloat16 g_xhi[(size_t)MAXN * HID];
__device__ __nv_bfloat16 g_xlo[(size_t)MAXN * HID];
__device__ __nv_bfloat16 g_yhi[(size_t)MAXN * HID];
__device__ __nv_bfloat16 g_ylo[(size_t)MAXN * HID];
__device__ __nv_bfloat16 g_h0hi[(size_t)MAXN * HID];
__device__ __nv_bfloat16 g_h0lo[(size_t)MAXN * HID];
__device__ __nv_bfloat16 g_agghi[(size_t)MAXN * HID];
__device__ __nv_bfloat16 g_agglo[(size_t)MAXN * HID];
__device__ int   g_cnt[MAXN + 1];
__device__ int   g_off[MAXN + 1];
__device__ int   g_fill[MAXN];
__device__ int   g_srcs[MAXE];
__device__ float g_pooled[NGRAPH * HID];
__device__ __nv_bfloat16 g_wthi[128 * 768];
__device__ __nv_bfloat16 g_wtlo[128 * 768];

// ---------------- tiny helpers ----------------
__device__ __forceinline__ void cpa16(unsigned dst, const void* src, int pbytes) {
    asm volatile("cp.async.cg.shared.global [%0], [%1], 16, %2;\n"
                 :: "r"(dst), "l"(src), "r"(pbytes));
}
__device__ __forceinline__ void cpa_commit() { asm volatile("cp.async.commit_group;\n"); }
__device__ __forceinline__ void cpa_wait0()  { asm volatile("cp.async.wait_group 0;\n"); }

__device__ __forceinline__ void mma16816(float c[4], const unsigned a[4], const unsigned* b) {
    asm volatile(
        "mma.sync.aligned.m16n8k16.row.col.f32.bf16.bf16.f32 "
        "{%0,%1,%2,%3},{%4,%5,%6,%7},{%8,%9},{%0,%1,%2,%3};"
        : "+f"(c[0]), "+f"(c[1]), "+f"(c[2]), "+f"(c[3])
        : "r"(a[0]), "r"(a[1]), "r"(a[2]), "r"(a[3]), "r"(b[0]), "r"(b[1]));
}
__device__ __forceinline__ void ldsm_x4(unsigned r[4], unsigned addr) {
    asm volatile("ldmatrix.sync.aligned.m8n8.x4.shared.b16 {%0,%1,%2,%3}, [%4];"
                 : "=r"(r[0]), "=r"(r[1]), "=r"(r[2]), "=r"(r[3]) : "r"(addr));
}

// ---------------- conversion kernels ----------------
__global__ void wconvert_all(const float* __restrict__ w0, const float* __restrict__ wa0,
                             const float* __restrict__ w1, const float* __restrict__ wa1,
                             __nv_bfloat16* __restrict__ hi, __nv_bfloat16* __restrict__ lo)
{
    const int r = blockIdx.y;
    const int K   = (r & 1) ? 256 : 128;
    const int off = (r == 0) ? 0 : (r == 1) ? 16384 : (r == 2) ? 49152 : 65536;
    const float* W = (r == 0) ? w0 : (r == 1) ? wa0 : (r == 2) ? w1 : wa1;
    int idx = blockIdx.x * blockDim.x + threadIdx.x;
    if (idx >= 128 * K) return;
    int n = idx / K, k = idx % K;
    float v = W[(size_t)k * 128 + n];
    __nv_bfloat16 h = __float2bfloat16(v);
    hi[off + idx] = h;
    lo[off + idx] = __float2bfloat16(v - __bfloat162float(h));
}

__global__ void xconvert_kernel(const float* __restrict__ x,
                                __nv_bfloat16* __restrict__ hi,
                                __nv_bfloat16* __restrict__ lo, int total4)
{
    int i = blockIdx.x * blockDim.x + threadIdx.x;
    if (i >= total4) return;
    float4 v = *(const float4*)(x + (size_t)i * 4);
    __nv_bfloat16 h0 = __float2bfloat16(v.x), h1 = __float2bfloat16(v.y);
    __nv_bfloat16 h2 = __float2bfloat16(v.z), h3 = __float2bfloat16(v.w);
    __nv_bfloat162 hp0(h0, h1), hp1(h2, h3);
    __nv_bfloat162 lp0(__float2bfloat16(v.x - __bfloat162float(h0)),
                       __float2bfloat16(v.y - __bfloat162float(h1)));
    __nv_bfloat162 lp1(__float2bfloat16(v.z - __bfloat162float(h2)),
                       __float2bfloat16(v.w - __bfloat162float(h3)));
    *(__nv_bfloat162*)(hi + (size_t)i * 4)     = hp0;
    *(__nv_bfloat162*)(hi + (size_t)i * 4 + 2) = hp1;
    *(__nv_bfloat162*)(lo + (size_t)i * 4)     = lp0;
    *(__nv_bfloat162*)(lo + (size_t)i * 4 + 2) = lp1;
}

// ---------------- CSR build ----------------
__global__ void zero_kernel(int* cnt, float* pooled, int ncnt, int npool) {
    int i = blockIdx.x * blockDim.x + threadIdx.x;
    if (i < ncnt)  cnt[i] = 0;
    if (i < npool) pooled[i] = 0.0f;
}
__global__ void hist_kernel(const int* __restrict__ dst, int* __restrict__ cnt, int E) {
    int e = blockIdx.x * blockDim.x + threadIdx.x;
    if (e < E) atomicAdd(&cnt[dst[e]], 1);
}
__global__ void scan_kernel(const int* __restrict__ cnt, int* __restrict__ off,
                            int* __restrict__ fill, int N) {
    __shared__ int warpsum[32];
    __shared__ int s_carry;
    const int tid = threadIdx.x;
    if (tid == 0) s_carry = 0;
    __syncthreads();
    for (int base = 0; base < N; base += 1024) {
        int i = base + tid;
        int v = (i < N) ? cnt[i] : 0;
        int x = v;
        #pragma unroll
        for (int d = 1; d < 32; d <<= 1) {
            int t = __shfl_up_sync(0xffffffffu, x, d);
            if ((tid & 31) >= d) x += t;
        }
        if ((tid & 31) == 31) warpsum[tid >> 5] = x;
        __syncthreads();
        if (tid < 32) {
            int w = warpsum[tid];
            #pragma unroll
            for (int d = 1; d < 32; d <<= 1) {
                int t = __shfl_up_sync(0xffffffffu, w, d);
                if (tid >= d) w += t;
            }
            warpsum[tid] = w;
        }
        __syncthreads();
        int warpOff = (tid >= 32) ? warpsum[(tid >> 5) - 1] : 0;
        int excl = s_carry + warpOff + x - v;
        if (i < N) { off[i] = excl; fill[i] = excl; }
        __syncthreads();
        if (tid == 0) s_carry += warpsum[31];
        __syncthreads();
    }
    if (tid == 0) off[N] = s_carry;
}
__global__ void fill_kernel(const int* __restrict__ src, const int* __restrict__ dst,
                            int* __restrict__ fill, int* __restrict__ srcs, int E) {
    int e = blockIdx.x * blockDim.x + threadIdx.x;
    if (e < E) {
        int p = atomicAdd(&fill[dst[e]], 1);
        srcs[p] = src[e];
    }
}

// ---------------- GEMM: 2-stage cp.async, 1 barrier/chunk, ldmatrix, fused pool ----------------
#define APAD 40
#define STG_ELEMS (4 * 128 * APAD)
#define SMEM_GEMM (2 * STG_ELEMS * 2 + 1024)

__device__ __forceinline__ void stage_chunk(
    const __nv_bfloat16* __restrict__ A1hi, const __nv_bfloat16* __restrict__ A1lo,
    const __nv_bfloat16* __restrict__ A2hi, const __nv_bfloat16* __restrict__ A2lo,
    const __nv_bfloat16* __restrict__ wthi, const __nv_bfloat16* __restrict__ wtlo,
    int Ktot, unsigned sbase, int kg, int rowBase, int M, int tid)
{
    const __nv_bfloat16* Ahi = (kg < 128) ? A1hi : A2hi;
    const __nv_bfloat16* Alo = (kg < 128) ? A1lo : A2lo;
    const int kk = (kg < 128) ? kg : kg - 128;
    #pragma unroll
    for (int p = 0; p < 2; ++p) {
        int idx = p * 256 + tid;
        int row = idx >> 2, seg = idx & 3;
        int g = rowBase + row;
        int pb = (g < M) ? 16 : 0;
        int gc = (g < M) ? g : 0;
        size_t so = (size_t)gc * 128 + kk + seg * 8;
        unsigned d = sbase + (row * APAD + seg * 8) * 2;
        cpa16(d,                  Ahi + so, pb);
        cpa16(d + 128 * APAD * 2, Alo + so, pb);
    }
    #pragma unroll
    for (int p = 0; p < 2; ++p) {
        int idx = p * 256 + tid;
        int n = idx >> 2, seg = idx & 3;
        size_t so = (size_t)n * Ktot + kg + seg * 8;
        unsigned d = sbase + (2 * 128 * APAD + n * APAD + seg * 8) * 2;
        cpa16(d,                  wthi + so, 16);
        cpa16(d + 128 * APAD * 2, wtlo + so, 16);
    }
}

__global__ __launch_bounds__(256, 2)
void gemm_mma(const __nv_bfloat16* __restrict__ A1hi, const __nv_bfloat16* __restrict__ A1lo,
              const __nv_bfloat16* __restrict__ A2hi, const __nv_bfloat16* __restrict__ A2lo,
              const __nv_bfloat16* __restrict__ wthi, const __nv_bfloat16* __restrict__ wtlo,
              int Ktot, const float* __restrict__ bias,
              __nv_bfloat16* __restrict__ Chi, __nv_bfloat16* __restrict__ Clo,
              const int* __restrict__ batch, float* __restrict__ pooled,
              int M, int doNorm)
{
    extern __shared__ __align__(16) __nv_bfloat16 smem[];
    float* rowss = (float*)(smem + 2 * STG_ELEMS);
    const unsigned sb = (unsigned)__cvta_generic_to_shared(smem);

    const int tid = threadIdx.x;
    const int wid = tid >> 5, lane = tid & 31;
    const int wm = wid & 3, wn = wid >> 2;
    const int g4 = lane >> 2, q = lane & 3;
    const int rowBase = blockIdx.x * 128;

    const int aRow = wm * 32 + (lane & 15);
    const int aCol = (lane & 16) ? 8 : 0;
    const unsigned aAddr0 = sb + (unsigned)(aRow * APAD + aCol) * 2;
    const int bRow = wn * 64 + (lane & 7) + ((lane & 16) ? 8 : 0);
    const int bCol = (lane & 8) ? 8 : 0;
    const unsigned bAddr0 = sb + (unsigned)(2 * 128 * APAD + bRow * APAD + bCol) * 2;
    const unsigned LOOFF = 128 * APAD * 2;
    const unsigned I16   = 16 * APAD * 2;

    float acc[2][8][4];
    #pragma unroll
    for (int i = 0; i < 2; ++i)
        #pragma unroll
        for (int j = 0; j < 8; ++j)
            #pragma unroll
            for (int v = 0; v < 4; ++v) acc[i][j][v] = 0.0f;

    const int nChunks = Ktot / 32;
    stage_chunk(A1hi, A1lo, A2hi, A2lo, wthi, wtlo, Ktot, sb, 0, rowBase, M, tid);
    cpa_commit();

    for (int kc = 0; kc < nChunks; ++kc) {
        cpa_wait0();
        __syncthreads();
        // issue next stage AFTER barrier (safe: all warps finished reading that buffer),
        // BEFORE compute (overlaps loads with MMA). One barrier per chunk.
        if (kc + 1 < nChunks) {
            stage_chunk(A1hi, A1lo, A2hi, A2lo, wthi, wtlo, Ktot,
                        sb + ((kc + 1) & 1) * STG_ELEMS * 2, (kc + 1) * 32, rowBase, M, tid);
            cpa_commit();
        }

        const unsigned stoff = ((unsigned)(kc & 1)) * STG_ELEMS * 2;
        #pragma unroll
        for (int k16 = 0; k16 < 2; ++k16) {
            const unsigned kb = (unsigned)k16 * 32;
            unsigned ah0[4], ah1[4], al0[4], al1[4];
            ldsm_x4(ah0, aAddr0 + stoff + kb);
            ldsm_x4(ah1, aAddr0 + stoff + kb + I16);
            ldsm_x4(al0, aAddr0 + stoff + kb + LOOFF);
            ldsm_x4(al1, aAddr0 + stoff + kb + LOOFF + I16);
            #pragma unroll
            for (int jj = 0; jj < 4; ++jj) {
                unsigned bh[4], bl[4];
                unsigned ba = bAddr0 + stoff + kb + (unsigned)jj * I16;
                ldsm_x4(bh, ba);
                ldsm_x4(bl, ba + LOOFF);
                mma16816(acc[0][2 * jj],     ah0, &bh[0]);
                mma16816(acc[1][2 * jj],     ah1, &bh[0]);
                mma16816(acc[0][2 * jj],     ah0, &bl[0]);
                mma16816(acc[1][2 * jj],     ah1, &bl[0]);
                mma16816(acc[0][2 * jj],     al0, &bh[0]);
                mma16816(acc[1][2 * jj],     al1, &bh[0]);
                mma16816(acc[0][2 * jj + 1], ah0, &bh[2]);
                mma16816(acc[1][2 * jj + 1], ah1, &bh[2]);
                mma16816(acc[0][2 * jj + 1], ah0, &bl[2]);
                mma16816(acc[1][2 * jj + 1], ah1, &bl[2]);
                mma16816(acc[0][2 * jj + 1], al0, &bh[2]);
                mma16816(acc[1][2 * jj + 1], al1, &bh[2]);
            }
        }
    }

    // ---- epilogue: bias + relu (+ L2 norm) ----
    #pragma unroll
    for (int j = 0; j < 8; ++j) {
        int col = wn * 64 + j * 8 + q * 2;
        float2 b = *(const float2*)(bias + col);
        #pragma unroll
        for (int i = 0; i < 2; ++i) {
            acc[i][j][0] = fmaxf(acc[i][j][0] + b.x, 0.0f);
            acc[i][j][1] = fmaxf(acc[i][j][1] + b.y, 0.0f);
            acc[i][j][2] = fmaxf(acc[i][j][2] + b.x, 0.0f);
            acc[i][j][3] = fmaxf(acc[i][j][3] + b.y, 0.0f);
        }
    }
    if (doNorm) {
        __syncthreads();   // protect rowss region vs any in-flight smem use
        #pragma unroll
        for (int i = 0; i < 2; ++i) {
            int r = wm * 32 + i * 16 + g4;
            float ssLo = 0.f, ssHi = 0.f;
            #pragma unroll
            for (int j = 0; j < 8; ++j) {
                ssLo += acc[i][j][0] * acc[i][j][0] + acc[i][j][1] * acc[i][j][1];
                ssHi += acc[i][j][2] * acc[i][j][2] + acc[i][j][3] * acc[i][j][3];
            }
            ssLo += __shfl_xor_sync(0xffffffffu, ssLo, 1);
            ssLo += __shfl_xor_sync(0xffffffffu, ssLo, 2);
            ssHi += __shfl_xor_sync(0xffffffffu, ssHi, 1);
            ssHi += __shfl_xor_sync(0xffffffffu, ssHi, 2);
            if (q == 0) { rowss[r * 2 + wn] = ssLo; rowss[(r + 8) * 2 + wn] = ssHi; }
        }
        __syncthreads();
        #pragma unroll
        for (int i = 0; i < 2; ++i) {
            int r = wm * 32 + i * 16 + g4;
            float invLo = 1.0f / fmaxf(sqrtf(rowss[r * 2] + rowss[r * 2 + 1]), 1e-12f);
            float invHi = 1.0f / fmaxf(sqrtf(rowss[(r + 8) * 2] + rowss[(r + 8) * 2 + 1]), 1e-12f);
            #pragma unroll
            for (int j = 0; j < 8; ++j) {
                acc[i][j][0] *= invLo; acc[i][j][1] *= invLo;
                acc[i][j][2] *= invHi; acc[i][j][3] *= invHi;
            }
        }
    }

    if (pooled) {
        // fused global max pool: values >= 0, pooled pre-zeroed -> int atomicMax valid
        #pragma unroll
        for (int i = 0; i < 2; ++i) {
            int r0 = rowBase + wm * 32 + i * 16 + g4;
            int r1 = r0 + 8;
            int b0 = (r0 < M) ? batch[r0] : 0;
            int b1 = (r1 < M) ? batch[r1] : 0;
            #pragma unroll
            for (int j = 0; j < 8; ++j) {
                int col = wn * 64 + j * 8 + q * 2;
                if (r0 < M) {
                    atomicMax((int*)&pooled[b0 * 128 + col],     __float_as_int(acc[i][j][0]));
                    atomicMax((int*)&pooled[b0 * 128 + col + 1], __float_as_int(acc[i][j][1]));
                }
                if (r1 < M) {
                    atomicMax((int*)&pooled[b1 * 128 + col],     __float_as_int(acc[i][j][2]));
                    atomicMax((int*)&pooled[b1 * 128 + col + 1], __float_as_int(acc[i][j][3]));
                }
            }
        }
        return;
    }

    // ---- hi/lo stores ----
    #pragma unroll
    for (int i = 0; i < 2; ++i) {
        int r0 = rowBase + wm * 32 + i * 16 + g4;
        #pragma unroll
        for (int j = 0; j < 8; ++j) {
            int col = wn * 64 + j * 8 + q * 2;
            __nv_bfloat16 h0 = __float2bfloat16(acc[i][j][0]);
            __nv_bfloat16 h1 = __float2bfloat16(acc[i][j][1]);
            __nv_bfloat16 h2 = __float2bfloat16(acc[i][j][2]);
            __nv_bfloat16 h3 = __float2bfloat16(acc[i][j][3]);
            __nv_bfloat162 lp0(__float2bfloat16(acc[i][j][0] - __bfloat162float(h0)),
                               __float2bfloat16(acc[i][j][1] - __bfloat162float(h1)));
            __nv_bfloat162 lp1(__float2bfloat16(acc[i][j][2] - __bfloat162float(h2)),
                               __float2bfloat16(acc[i][j][3] - __bfloat162float(h3)));
            if (r0 < M) {
                *(__nv_bfloat162*)(Chi + (size_t)r0 * 128 + col) = __nv_bfloat162(h0, h1);
                *(__nv_bfloat162*)(Clo + (size_t)r0 * 128 + col) = lp0;
            }
            if (r0 + 8 < M) {
                *(__nv_bfloat162*)(Chi + (size_t)(r0 + 8) * 128 + col) = __nv_bfloat162(h2, h3);
                *(__nv_bfloat162*)(Clo + (size_t)(r0 + 8) * 128 + col) = lp1;
            }
        }
    }
}

// ---------------- CSR mean aggregation (bf16 hi/lo): lane handles 4 features ----------------
__global__ void agg_kernel(const __nv_bfloat16* __restrict__ yhi,
                           const __nv_bfloat16* __restrict__ ylo,
                           __nv_bfloat16* __restrict__ ahi,
                           __nv_bfloat16* __restrict__ alo,
                           const int* __restrict__ off, const int* __restrict__ srcs,
                           int N)
{
    int w = (blockIdx.x * blockDim.x + threadIdx.x) >> 5;
    int lane = threadIdx.x & 31;
    if (w >= N) return;
    int s0 = off[w], s1 = off[w + 1];
    float acc0 = 0.f, acc1 = 0.f, acc2 = 0.f, acc3 = 0.f;
    int i = s0;
    for (; i + 1 < s1; i += 2) {
        int sA = __ldg(&srcs[i]);
        int sB = __ldg(&srcs[i + 1]);
        uint2 hA = *(const uint2*)(yhi + (size_t)sA * 128 + lane * 4);
        uint2 lA = *(const uint2*)(ylo + (size_t)sA * 128 + lane * 4);
        uint2 hB = *(const uint2*)(yhi + (size_t)sB * 128 + lane * 4);
        uint2 lB = *(const uint2*)(ylo + (size_t)sB * 128 + lane * 4);
        float2 a = __bfloat1622float2(*(const __nv_bfloat162*)&hA.x);
        float2 b = __bfloat1622float2(*(const __nv_bfloat162*)&hA.y);
        float2 c = __bfloat1622float2(*(const __nv_bfloat162*)&lA.x);
        float2 d = __bfloat1622float2(*(const __nv_bfloat162*)&lA.y);
        acc0 += a.x + c.x; acc1 += a.y + c.y; acc2 += b.x + d.x; acc3 += b.y + d.y;
        a = __bfloat1622float2(*(const __nv_bfloat162*)&hB.x);
        b = __bfloat1622float2(*(const __nv_bfloat162*)&hB.y);
        c = __bfloat1622float2(*(const __nv_bfloat162*)&lB.x);
        d = __bfloat1622float2(*(const __nv_bfloat162*)&lB.y);
        acc0 += a.x + c.x; acc1 += a.y + c.y; acc2 += b.x + d.x; acc3 += b.y + d.y;
    }
    if (i < s1) {
        int sA = __ldg(&srcs[i]);
        uint2 hA = *(const uint2*)(yhi + (size_t)sA * 128 + lane * 4);
        uint2 lA = *(const uint2*)(ylo + (size_t)sA * 128 + lane * 4);
        float2 a = __bfloat1622float2(*(const __nv_bfloat162*)&hA.x);
        float2 b = __bfloat1622float2(*(const __nv_bfloat162*)&hA.y);
        float2 c = __bfloat1622float2(*(const __nv_bfloat162*)&lA.x);
        float2 d = __bfloat1622float2(*(const __nv_bfloat162*)&lA.y);
        acc0 += a.x + c.x; acc1 += a.y + c.y; acc2 += b.x + d.x; acc3 += b.y + d.y;
    }
    float inv = 1.0f / fmaxf((float)(s1 - s0), 1.0f);
    acc0 *= inv; acc1 *= inv; acc2 *= inv; acc3 *= inv;
    __nv_bfloat16 h0 = __float2bfloat16(acc0), h1 = __float2bfloat16(acc1);
    __nv_bfloat16 h2 = __float2bfloat16(acc2), h3 = __float2bfloat16(acc3);
    __nv_bfloat162 hp0(h0, h1), hp1(h2, h3);
    __nv_bfloat162 lp0(__float2bfloat16(acc0 - __bfloat162float(h0)),
                       __float2bfloat16(acc1 - __bfloat162float(h1)));
    __nv_bfloat162 lp1(__float2bfloat16(acc2 - __bfloat162float(h2)),
                       __float2bfloat16(acc3 - __bfloat162float(h3)));
    *(__nv_bfloat162*)(ahi + (size_t)w * 128 + lane * 4)     = hp0;
    *(__nv_bfloat162*)(ahi + (size_t)w * 128 + lane * 4 + 2) = hp1;
    *(__nv_bfloat162*)(alo + (size_t)w * 128 + lane * 4)     = lp0;
    *(__nv_bfloat162*)(alo + (size_t)w * 128 + lane * 4 + 2) = lp1;
}

// ---------------- head ----------------
__global__ void head_kernel(const float* __restrict__ pooled,
                            const float* __restrict__ w1, const float* __restrict__ b1,
                            const float* __restrict__ w2, const float* __restrict__ b2,
                            float* __restrict__ out)
{
    __shared__ float t[NGRAPH][HID];
    int tid = threadIdx.x;
    for (int o = tid; o < NGRAPH * HID; o += blockDim.x) {
        int r = o >> 7, c = o & 127;
        float s = b1[c];
        #pragma unroll 8
        for (int k = 0; k < 128; ++k) s = fmaf(pooled[r * 128 + k], w1[k * 128 + c], s);
        t[r][c] = s;
    }
    __syncthreads();
    if (tid < NGRAPH) {
        float z0 = b2[0], z1 = b2[1];
        #pragma unroll 8
        for (int k = 0; k < 128; ++k) {
            float v = t[tid][k];
            z0 = fmaf(v, w2[k * 2 + 0], z0);
            z1 = fmaf(v, w2[k * 2 + 1], z1);
        }
        float m = fmaxf(z0, z1);
        float lse = m + logf(expf(z0 - m) + expf(z1 - m));
        out[tid * 2 + 0] = z0 - lse;
        out[tid * 2 + 1] = z1 - lse;
    }
}

// ---------------- launch ----------------
extern "C" void kernel_launch(void* const* d_in, const int* in_sizes, int n_in,
                              void* d_out, int out_size)
{
    const float* x      = (const float*)d_in[0];
    const int*   ei     = (const int*)  d_in[1];
    const int*   batch  = (const int*)  d_in[2];
    const float* lin_w0 = (const float*)d_in[3];
    const float* lin_b0 = (const float*)d_in[4];
    const float* agg_w0 = (const float*)d_in[5];
    const float* agg_b0 = (const float*)d_in[6];
    const float* lin_w1 = (const float*)d_in[7];
    const float* lin_b1 = (const float*)d_in[8];
    const float* agg_w1 = (const float*)d_in[9];
    const float* agg_b1 = (const float*)d_in[10];
    const float* mp_w1  = (const float*)d_in[11];
    const float* mp_b1  = (const float*)d_in[12];
    const float* mp_w2  = (const float*)d_in[13];
    const float* mp_b2  = (const float*)d_in[14];
    float* out = (float*)d_out;

    const int N = in_sizes[0] / HID;
    const int E = in_sizes[1] / 2;
    const int* src = ei;
    const int* dst = ei + E;

    void *p;
    float *pooled;
    int *cnt, *off, *fill, *srcs;
    __nv_bfloat16 *xhi, *xlo, *yhi, *ylo, *h0hi, *h0lo, *ahi, *alo, *wthi, *wtlo;
    cudaGetSymbolAddress(&p, g_pooled); pooled = (float*)p;
    cudaGetSymbolAddress(&p, g_cnt);    cnt    = (int*)p;
    cudaGetSymbolAddress(&p, g_off);    off    = (int*)p;
    cudaGetSymbolAddress(&p, g_fill);   fill   = (int*)p;
    cudaGetSymbolAddress(&p, g_srcs);   srcs   = (int*)p;
    cudaGetSymbolAddress(&p, g_xhi);    xhi    = (__nv_bfloat16*)p;
    cudaGetSymbolAddress(&p, g_xlo);    xlo    = (__nv_bfloat16*)p;
    cudaGetSymbolAddress(&p, g_yhi);    yhi    = (__nv_bfloat16*)p;
    cudaGetSymbolAddress(&p, g_ylo);    ylo    = (__nv_bfloat16*)p;
    cudaGetSymbolAddress(&p, g_h0hi);   h0hi   = (__nv_bfloat16*)p;
    cudaGetSymbolAddress(&p, g_h0lo);   h0lo   = (__nv_bfloat16*)p;
    cudaGetSymbolAddress(&p, g_agghi);  ahi    = (__nv_bfloat16*)p;
    cudaGetSymbolAddress(&p, g_agglo);  alo    = (__nv_bfloat16*)p;
    cudaGetSymbolAddress(&p, g_wthi);   wthi   = (__nv_bfloat16*)p;
    cudaGetSymbolAddress(&p, g_wtlo);   wtlo   = (__nv_bfloat16*)p;

    cudaFuncSetAttribute(gemm_mma, cudaFuncAttributeMaxDynamicSharedMemorySize, SMEM_GEMM);

    const int gridM = (N + 127) / 128;
    const int zeroN = (N + 1 > NGRAPH * HID) ? (N + 1) : NGRAPH * HID;

    // launch 1-3: converts + zero
    {
        dim3 g((128 * 256 + 255) / 256, 4);
        wconvert_all<<<g, 256>>>(lin_w0, agg_w0, lin_w1, agg_w1, wthi, wtlo);
    }
    xconvert_kernel<<<(N * 32 + 255) / 256, 256>>>(x, xhi, xlo, N * 32);
    zero_kernel<<<(zeroN + 255) / 256, 256>>>(cnt, pooled, N + 1, NGRAPH * HID);

    // launch 4: first GEMM (ncu capture slot)
    gemm_mma<<<gridM, 256, SMEM_GEMM>>>(xhi, xlo, nullptr, nullptr,
                                        wthi, wtlo, 128, lin_b0,
                                        yhi, ylo, nullptr, nullptr, N, 0);

    // launches 5-7: CSR build
    hist_kernel<<<(E + 255) / 256, 256>>>(dst, cnt, E);
    scan_kernel<<<1, 1024>>>(cnt, off, fill, N);
    fill_kernel<<<(E + 255) / 256, 256>>>(src, dst, fill, srcs, E);

    // layer 0
    agg_kernel<<<(N + 7) / 8, 256>>>(yhi, ylo, ahi, alo, off, srcs, N);
    gemm_mma<<<gridM, 256, SMEM_GEMM>>>(ahi, alo, xhi, xlo,
                                        wthi + 16384, wtlo + 16384, 256, agg_b0,
                                        h0hi, h0lo, nullptr, nullptr, N, 1);
    // layer 1
    gemm_mma<<<gridM, 256, SMEM_GEMM>>>(h0hi, h0lo, nullptr, nullptr,
                                        wthi + 49152, wtlo + 49152, 128, lin_b1,
                                        yhi, ylo, nullptr, nullptr, N, 0);
    agg_kernel<<<(N + 7) / 8, 256>>>(yhi, ylo, ahi, alo, off, srcs, N);
    // final GEMM: norm + fused max-pool (no tensor store)
    gemm_mma<<<gridM, 256, SMEM_GEMM>>>(ahi, alo, h0hi, h0lo,
                                        wthi + 65536, wtlo + 65536, 256, agg_b1,
                                        nullptr, nullptr, batch, pooled, N, 1);

    // head
    head_kernel<<<1, 256>>>(pooled, mp_w1, mp_b1, mp_w2, mp_b2, out);
}

// round 7
// speedup vs baseline: 1.0619x; 1.0619x over previous
#include <cuda_runtime.h>
#include <cuda_bf16.h>
#include <math.h>

#define MAXN 50000
#define MAXE 600000
#define HID 128
#define NGRAPH 64

// ---------------- scratch (static device globals) ----------------
__device__ __nv_bfloat16 g_xhi[(size_t)MAXN * HID];
__device__ __nv_bfloat16 g_xlo[(size_t)MAXN * HID];
__device__ __nv_bfloat16 g_yhi[(size_t)MAXN * HID];
__device__ __nv_bfloat16 g_ylo[(size_t)MAXN * HID];
__device__ __nv_bfloat16 g_h0hi[(size_t)MAXN * HID];
__device__ __nv_bfloat16 g_h0lo[(size_t)MAXN * HID];
__device__ __nv_bfloat16 g_agghi[(size_t)MAXN * HID];
__device__ __nv_bfloat16 g_agglo[(size_t)MAXN * HID];
__device__ float g_y[(size_t)MAXN * HID];        // final layer fp32 (pool input)
__device__ int   g_cnt[MAXN + 1];
__device__ int   g_off[MAXN + 1];
__device__ int   g_fill[MAXN];
__device__ int   g_srcs[MAXE];
__device__ float g_pooled[NGRAPH * HID];
__device__ __nv_bfloat16 g_wthi[128 * 768];
__device__ __nv_bfloat16 g_wtlo[128 * 768];

// ---------------- tiny helpers ----------------
__device__ __forceinline__ void cpa16(unsigned dst, const void* src, int pbytes) {
    asm volatile("cp.async.cg.shared.global [%0], [%1], 16, %2;\n"
                 :: "r"(dst), "l"(src), "r"(pbytes));
}
__device__ __forceinline__ void cpa_commit() { asm volatile("cp.async.commit_group;\n"); }
__device__ __forceinline__ void cpa_wait0()  { asm volatile("cp.async.wait_group 0;\n"); }

__device__ __forceinline__ void mma16816(float c[4], const unsigned a[4], const unsigned* b) {
    asm volatile(
        "mma.sync.aligned.m16n8k16.row.col.f32.bf16.bf16.f32 "
        "{%0,%1,%2,%3},{%4,%5,%6,%7},{%8,%9},{%0,%1,%2,%3};"
        : "+f"(c[0]), "+f"(c[1]), "+f"(c[2]), "+f"(c[3])
        : "r"(a[0]), "r"(a[1]), "r"(a[2]), "r"(a[3]), "r"(b[0]), "r"(b[1]));
}
__device__ __forceinline__ void ldsm_x4(unsigned r[4], unsigned addr) {
    asm volatile("ldmatrix.sync.aligned.m8n8.x4.shared.b16 {%0,%1,%2,%3}, [%4];"
                 : "=r"(r[0]), "=r"(r[1]), "=r"(r[2]), "=r"(r[3]) : "r"(addr));
}

// ---------------- conversion kernels ----------------
__global__ void wconvert_all(const float* __restrict__ w0, const float* __restrict__ wa0,
                             const float* __restrict__ w1, const float* __restrict__ wa1,
                             __nv_bfloat16* __restrict__ hi, __nv_bfloat16* __restrict__ lo)
{
    const int r = blockIdx.y;
    const int K   = (r & 1) ? 256 : 128;
    const int off = (r == 0) ? 0 : (r == 1) ? 16384 : (r == 2) ? 49152 : 65536;
    const float* W = (r == 0) ? w0 : (r == 1) ? wa0 : (r == 2) ? w1 : wa1;
    int idx = blockIdx.x * blockDim.x + threadIdx.x;
    if (idx >= 128 * K) return;
    int n = idx / K, k = idx % K;
    float v = W[(size_t)k * 128 + n];
    __nv_bfloat16 h = __float2bfloat16(v);
    hi[off + idx] = h;
    lo[off + idx] = __float2bfloat16(v - __bfloat162float(h));
}

__global__ void xconvert_kernel(const float* __restrict__ x,
                                __nv_bfloat16* __restrict__ hi,
                                __nv_bfloat16* __restrict__ lo, int total4)
{
    int i = blockIdx.x * blockDim.x + threadIdx.x;
    if (i >= total4) return;
    float4 v = *(const float4*)(x + (size_t)i * 4);
    __nv_bfloat16 h0 = __float2bfloat16(v.x), h1 = __float2bfloat16(v.y);
    __nv_bfloat16 h2 = __float2bfloat16(v.z), h3 = __float2bfloat16(v.w);
    __nv_bfloat162 hp0(h0, h1), hp1(h2, h3);
    __nv_bfloat162 lp0(__float2bfloat16(v.x - __bfloat162float(h0)),
                       __float2bfloat16(v.y - __bfloat162float(h1)));
    __nv_bfloat162 lp1(__float2bfloat16(v.z - __bfloat162float(h2)),
                       __float2bfloat16(v.w - __bfloat162float(h3)));
    *(__nv_bfloat162*)(hi + (size_t)i * 4)     = hp0;
    *(__nv_bfloat162*)(hi + (size_t)i * 4 + 2) = hp1;
    *(__nv_bfloat162*)(lo + (size_t)i * 4)     = lp0;
    *(__nv_bfloat162*)(lo + (size_t)i * 4 + 2) = lp1;
}

// ---------------- CSR build ----------------
__global__ void zero_kernel(int* cnt, float* pooled, int ncnt, int npool) {
    int i = blockIdx.x * blockDim.x + threadIdx.x;
    if (i < ncnt)  cnt[i] = 0;
    if (i < npool) pooled[i] = 0.0f;
}
__global__ void hist_kernel(const int* __restrict__ dst, int* __restrict__ cnt, int E) {
    int e = blockIdx.x * blockDim.x + threadIdx.x;
    if (e < E) atomicAdd(&cnt[dst[e]], 1);
}
__global__ void scan_kernel(const int* __restrict__ cnt, int* __restrict__ off,
                            int* __restrict__ fill, int N) {
    __shared__ int warpsum[32];
    __shared__ int s_carry;
    const int tid = threadIdx.x;
    if (tid == 0) s_carry = 0;
    __syncthreads();
    for (int base = 0; base < N; base += 1024) {
        int i = base + tid;
        int v = (i < N) ? cnt[i] : 0;
        int x = v;
        #pragma unroll
        for (int d = 1; d < 32; d <<= 1) {
            int t = __shfl_up_sync(0xffffffffu, x, d);
            if ((tid & 31) >= d) x += t;
        }
        if ((tid & 31) == 31) warpsum[tid >> 5] = x;
        __syncthreads();
        if (tid < 32) {
            int w = warpsum[tid];
            #pragma unroll
            for (int d = 1; d < 32; d <<= 1) {
                int t = __shfl_up_sync(0xffffffffu, w, d);
                if (tid >= d) w += t;
            }
            warpsum[tid] = w;
        }
        __syncthreads();
        int warpOff = (tid >= 32) ? warpsum[(tid >> 5) - 1] : 0;
        int excl = s_carry + warpOff + x - v;
        if (i < N) { off[i] = excl; fill[i] = excl; }
        __syncthreads();
        if (tid == 0) s_carry += warpsum[31];
        __syncthreads();
    }
    if (tid == 0) off[N] = s_carry;
}
__global__ void fill_kernel(const int* __restrict__ src, const int* __restrict__ dst,
                            int* __restrict__ fill, int* __restrict__ srcs, int E) {
    int e = blockIdx.x * blockDim.x + threadIdx.x;
    if (e < E) {
        int p = atomicAdd(&fill[dst[e]], 1);
        srcs[p] = src[e];
    }
}

// ---------------- GEMM: 2-stage cp.async, 1 barrier/chunk, ldmatrix, ILP-ordered MMA ----------------
#define APAD 40
#define STG_ELEMS (4 * 128 * APAD)
#define SMEM_GEMM (2 * STG_ELEMS * 2 + 1024)

__device__ __forceinline__ void stage_chunk(
    const __nv_bfloat16* __restrict__ A1hi, const __nv_bfloat16* __restrict__ A1lo,
    const __nv_bfloat16* __restrict__ A2hi, const __nv_bfloat16* __restrict__ A2lo,
    const __nv_bfloat16* __restrict__ wthi, const __nv_bfloat16* __restrict__ wtlo,
    int Ktot, unsigned sbase, int kg, int rowBase, int M, int tid)
{
    const __nv_bfloat16* Ahi = (kg < 128) ? A1hi : A2hi;
    const __nv_bfloat16* Alo = (kg < 128) ? A1lo : A2lo;
    const int kk = (kg < 128) ? kg : kg - 128;
    #pragma unroll
    for (int p = 0; p < 2; ++p) {
        int idx = p * 256 + tid;
        int row = idx >> 2, seg = idx & 3;
        int g = rowBase + row;
        int pb = (g < M) ? 16 : 0;
        int gc = (g < M) ? g : 0;
        size_t so = (size_t)gc * 128 + kk + seg * 8;
        unsigned d = sbase + (row * APAD + seg * 8) * 2;
        cpa16(d,                  Ahi + so, pb);
        cpa16(d + 128 * APAD * 2, Alo + so, pb);
    }
    #pragma unroll
    for (int p = 0; p < 2; ++p) {
        int idx = p * 256 + tid;
        int n = idx >> 2, seg = idx & 3;
        size_t so = (size_t)n * Ktot + kg + seg * 8;
        unsigned d = sbase + (2 * 128 * APAD + n * APAD + seg * 8) * 2;
        cpa16(d,                  wthi + so, 16);
        cpa16(d + 128 * APAD * 2, wtlo + so, 16);
    }
}

__global__ __launch_bounds__(256, 2)
void gemm_mma(const __nv_bfloat16* __restrict__ A1hi, const __nv_bfloat16* __restrict__ A1lo,
              const __nv_bfloat16* __restrict__ A2hi, const __nv_bfloat16* __restrict__ A2lo,
              const __nv_bfloat16* __restrict__ wthi, const __nv_bfloat16* __restrict__ wtlo,
              int Ktot, const float* __restrict__ bias,
              float* __restrict__ Cf, __nv_bfloat16* __restrict__ Chi,
              __nv_bfloat16* __restrict__ Clo, int M, int doNorm)
{
    extern __shared__ __align__(16) __nv_bfloat16 smem[];
    float* rowss = (float*)(smem + 2 * STG_ELEMS);
    const unsigned sb = (unsigned)__cvta_generic_to_shared(smem);

    const int tid = threadIdx.x;
    const int wid = tid >> 5, lane = tid & 31;
    const int wm = wid & 3, wn = wid >> 2;
    const int g4 = lane >> 2, q = lane & 3;
    const int rowBase = blockIdx.x * 128;

    const int aRow = wm * 32 + (lane & 15);
    const int aCol = (lane & 16) ? 8 : 0;
    const unsigned aAddr0 = sb + (unsigned)(aRow * APAD + aCol) * 2;
    const int bRow = wn * 64 + (lane & 7) + ((lane & 16) ? 8 : 0);
    const int bCol = (lane & 8) ? 8 : 0;
    const unsigned bAddr0 = sb + (unsigned)(2 * 128 * APAD + bRow * APAD + bCol) * 2;
    const unsigned LOOFF = 128 * APAD * 2;
    const unsigned I16   = 16 * APAD * 2;

    float acc[2][8][4];
    #pragma unroll
    for (int i = 0; i < 2; ++i)
        #pragma unroll
        for (int j = 0; j < 8; ++j)
            #pragma unroll
            for (int v = 0; v < 4; ++v) acc[i][j][v] = 0.0f;

    const int nChunks = Ktot / 32;
    stage_chunk(A1hi, A1lo, A2hi, A2lo, wthi, wtlo, Ktot, sb, 0, rowBase, M, tid);
    cpa_commit();

    for (int kc = 0; kc < nChunks; ++kc) {
        cpa_wait0();
        __syncthreads();
        if (kc + 1 < nChunks) {
            stage_chunk(A1hi, A1lo, A2hi, A2lo, wthi, wtlo, Ktot,
                        sb + ((kc + 1) & 1) * STG_ELEMS * 2, (kc + 1) * 32, rowBase, M, tid);
            cpa_commit();
        }

        const unsigned stoff = ((unsigned)(kc & 1)) * STG_ELEMS * 2;
        #pragma unroll
        for (int k16 = 0; k16 < 2; ++k16) {
            const unsigned kb = (unsigned)k16 * 32;
            // ---- load ALL fragments for this k16 step ----
            unsigned ah0[4], ah1[4], al0[4], al1[4];
            ldsm_x4(ah0, aAddr0 + stoff + kb);
            ldsm_x4(ah1, aAddr0 + stoff + kb + I16);
            ldsm_x4(al0, aAddr0 + stoff + kb + LOOFF);
            ldsm_x4(al1, aAddr0 + stoff + kb + LOOFF + I16);
            unsigned bh[4][4], bl[4][4];
            #pragma unroll
            for (int jj = 0; jj < 4; ++jj) {
                unsigned ba = bAddr0 + stoff + kb + (unsigned)jj * I16;
                ldsm_x4(bh[jj], ba);
                ldsm_x4(bl[jj], ba + LOOFF);
            }
            // ---- pass 1: ah x bh (16 independent MMAs) ----
            #pragma unroll
            for (int jj = 0; jj < 4; ++jj) {
                mma16816(acc[0][2 * jj],     ah0, &bh[jj][0]);
                mma16816(acc[1][2 * jj],     ah1, &bh[jj][0]);
                mma16816(acc[0][2 * jj + 1], ah0, &bh[jj][2]);
                mma16816(acc[1][2 * jj + 1], ah1, &bh[jj][2]);
            }
            // ---- pass 2: ah x bl ----
            #pragma unroll
            for (int jj = 0; jj < 4; ++jj) {
                mma16816(acc[0][2 * jj],     ah0, &bl[jj][0]);
                mma16816(acc[1][2 * jj],     ah1, &bl[jj][0]);
                mma16816(acc[0][2 * jj + 1], ah0, &bl[jj][2]);
                mma16816(acc[1][2 * jj + 1], ah1, &bl[jj][2]);
            }
            // ---- pass 3: al x bh ----
            #pragma unroll
            for (int jj = 0; jj < 4; ++jj) {
                mma16816(acc[0][2 * jj],     al0, &bh[jj][0]);
                mma16816(acc[1][2 * jj],     al1, &bh[jj][0]);
                mma16816(acc[0][2 * jj + 1], al0, &bh[jj][2]);
                mma16816(acc[1][2 * jj + 1], al1, &bh[jj][2]);
            }
        }
    }

    // ---- epilogue: bias + relu (+ L2 norm) ----
    #pragma unroll
    for (int j = 0; j < 8; ++j) {
        int col = wn * 64 + j * 8 + q * 2;
        float2 b = *(const float2*)(bias + col);
        #pragma unroll
        for (int i = 0; i < 2; ++i) {
            acc[i][j][0] = fmaxf(acc[i][j][0] + b.x, 0.0f);
            acc[i][j][1] = fmaxf(acc[i][j][1] + b.y, 0.0f);
            acc[i][j][2] = fmaxf(acc[i][j][2] + b.x, 0.0f);
            acc[i][j][3] = fmaxf(acc[i][j][3] + b.y, 0.0f);
        }
    }
    if (doNorm) {
        __syncthreads();
        #pragma unroll
        for (int i = 0; i < 2; ++i) {
            int r = wm * 32 + i * 16 + g4;
            float ssLo = 0.f, ssHi = 0.f;
            #pragma unroll
            for (int j = 0; j < 8; ++j) {
                ssLo += acc[i][j][0] * acc[i][j][0] + acc[i][j][1] * acc[i][j][1];
                ssHi += acc[i][j][2] * acc[i][j][2] + acc[i][j][3] * acc[i][j][3];
            }
            ssLo += __shfl_xor_sync(0xffffffffu, ssLo, 1);
            ssLo += __shfl_xor_sync(0xffffffffu, ssLo, 2);
            ssHi += __shfl_xor_sync(0xffffffffu, ssHi, 1);
            ssHi += __shfl_xor_sync(0xffffffffu, ssHi, 2);
            if (q == 0) { rowss[r * 2 + wn] = ssLo; rowss[(r + 8) * 2 + wn] = ssHi; }
        }
        __syncthreads();
        #pragma unroll
        for (int i = 0; i < 2; ++i) {
            int r = wm * 32 + i * 16 + g4;
            float invLo = 1.0f / fmaxf(sqrtf(rowss[r * 2] + rowss[r * 2 + 1]), 1e-12f);
            float invHi = 1.0f / fmaxf(sqrtf(rowss[(r + 8) * 2] + rowss[(r + 8) * 2 + 1]), 1e-12f);
            #pragma unroll
            for (int j = 0; j < 8; ++j) {
                acc[i][j][0] *= invLo; acc[i][j][1] *= invLo;
                acc[i][j][2] *= invHi; acc[i][j][3] *= invHi;
            }
        }
    }

    // ---- stores ----
    #pragma unroll
    for (int i = 0; i < 2; ++i) {
        int r0 = rowBase + wm * 32 + i * 16 + g4;
        #pragma unroll
        for (int j = 0; j < 8; ++j) {
            int col = wn * 64 + j * 8 + q * 2;
            if (Chi) {
                __nv_bfloat16 h0 = __float2bfloat16(acc[i][j][0]);
                __nv_bfloat16 h1 = __float2bfloat16(acc[i][j][1]);
                __nv_bfloat16 h2 = __float2bfloat16(acc[i][j][2]);
                __nv_bfloat16 h3 = __float2bfloat16(acc[i][j][3]);
                __nv_bfloat162 lp0(__float2bfloat16(acc[i][j][0] - __bfloat162float(h0)),
                                   __float2bfloat16(acc[i][j][1] - __bfloat162float(h1)));
                __nv_bfloat162 lp1(__float2bfloat16(acc[i][j][2] - __bfloat162float(h2)),
                                   __float2bfloat16(acc[i][j][3] - __bfloat162float(h3)));
                if (r0 < M) {
                    *(__nv_bfloat162*)(Chi + (size_t)r0 * 128 + col) = __nv_bfloat162(h0, h1);
                    *(__nv_bfloat162*)(Clo + (size_t)r0 * 128 + col) = lp0;
                }
                if (r0 + 8 < M) {
                    *(__nv_bfloat162*)(Chi + (size_t)(r0 + 8) * 128 + col) = __nv_bfloat162(h2, h3);
                    *(__nv_bfloat162*)(Clo + (size_t)(r0 + 8) * 128 + col) = lp1;
                }
            }
            if (Cf) {
                if (r0 < M)
                    *(float2*)(Cf + (size_t)r0 * 128 + col) = make_float2(acc[i][j][0], acc[i][j][1]);
                if (r0 + 8 < M)
                    *(float2*)(Cf + (size_t)(r0 + 8) * 128 + col) = make_float2(acc[i][j][2], acc[i][j][3]);
            }
        }
    }
}

// ---------------- CSR mean aggregation (bf16 hi/lo): lane handles 4 features ----------------
__global__ void agg_kernel(const __nv_bfloat16* __restrict__ yhi,
                           const __nv_bfloat16* __restrict__ ylo,
                           __nv_bfloat16* __restrict__ ahi,
                           __nv_bfloat16* __restrict__ alo,
                           const int* __restrict__ off, const int* __restrict__ srcs,
                           int N)
{
    int w = (blockIdx.x * blockDim.x + threadIdx.x) >> 5;
    int lane = threadIdx.x & 31;
    if (w >= N) return;
    int s0 = off[w], s1 = off[w + 1];
    float acc0 = 0.f, acc1 = 0.f, acc2 = 0.f, acc3 = 0.f;
    int i = s0;
    for (; i + 1 < s1; i += 2) {
        int sA = __ldg(&srcs[i]);
        int sB = __ldg(&srcs[i + 1]);
        uint2 hA = *(const uint2*)(yhi + (size_t)sA * 128 + lane * 4);
        uint2 lA = *(const uint2*)(ylo + (size_t)sA * 128 + lane * 4);
        uint2 hB = *(const uint2*)(yhi + (size_t)sB * 128 + lane * 4);
        uint2 lB = *(const uint2*)(ylo + (size_t)sB * 128 + lane * 4);
        float2 a = __bfloat1622float2(*(const __nv_bfloat162*)&hA.x);
        float2 b = __bfloat1622float2(*(const __nv_bfloat162*)&hA.y);
        float2 c = __bfloat1622float2(*(const __nv_bfloat162*)&lA.x);
        float2 d = __bfloat1622float2(*(const __nv_bfloat162*)&lA.y);
        acc0 += a.x + c.x; acc1 += a.y + c.y; acc2 += b.x + d.x; acc3 += b.y + d.y;
        a = __bfloat1622float2(*(const __nv_bfloat162*)&hB.x);
        b = __bfloat1622float2(*(const __nv_bfloat162*)&hB.y);
        c = __bfloat1622float2(*(const __nv_bfloat162*)&lB.x);
        d = __bfloat1622float2(*(const __nv_bfloat162*)&lB.y);
        acc0 += a.x + c.x; acc1 += a.y + c.y; acc2 += b.x + d.x; acc3 += b.y + d.y;
    }
    if (i < s1) {
        int sA = __ldg(&srcs[i]);
        uint2 hA = *(const uint2*)(yhi + (size_t)sA * 128 + lane * 4);
        uint2 lA = *(const uint2*)(ylo + (size_t)sA * 128 + lane * 4);
        float2 a = __bfloat1622float2(*(const __nv_bfloat162*)&hA.x);
        float2 b = __bfloat1622float2(*(const __nv_bfloat162*)&hA.y);
        float2 c = __bfloat1622float2(*(const __nv_bfloat162*)&lA.x);
        float2 d = __bfloat1622float2(*(const __nv_bfloat162*)&lA.y);
        acc0 += a.x + c.x; acc1 += a.y + c.y; acc2 += b.x + d.x; acc3 += b.y + d.y;
    }
    float inv = 1.0f / fmaxf((float)(s1 - s0), 1.0f);
    acc0 *= inv; acc1 *= inv; acc2 *= inv; acc3 *= inv;
    __nv_bfloat16 h0 = __float2bfloat16(acc0), h1 = __float2bfloat16(acc1);
    __nv_bfloat16 h2 = __float2bfloat16(acc2), h3 = __float2bfloat16(acc3);
    __nv_bfloat162 hp0(h0, h1), hp1(h2, h3);
    __nv_bfloat162 lp0(__float2bfloat16(acc0 - __bfloat162float(h0)),
                       __float2bfloat16(acc1 - __bfloat162float(h1)));
    __nv_bfloat162 lp1(__float2bfloat16(acc2 - __bfloat162float(h2)),
                       __float2bfloat16(acc3 - __bfloat162float(h3)));
    *(__nv_bfloat162*)(ahi + (size_t)w * 128 + lane * 4)     = hp0;
    *(__nv_bfloat162*)(ahi + (size_t)w * 128 + lane * 4 + 2) = hp1;
    *(__nv_bfloat162*)(alo + (size_t)w * 128 + lane * 4)     = lp0;
    *(__nv_bfloat162*)(alo + (size_t)w * 128 + lane * 4 + 2) = lp1;
}

// ---------------- global max pool (batch sorted) ----------------
#define POOL_CHUNK 128
__global__ void pool_kernel(const float* __restrict__ h, const int* __restrict__ batch,
                            float* __restrict__ pooled, int N)
{
    int j  = threadIdx.x;
    int n0 = blockIdx.x * POOL_CHUNK;
    int n1 = min(n0 + POOL_CHUNK, N);
    if (n0 >= N) return;
    int cur = batch[n0];
    float m = 0.0f;
    for (int n = n0; n < n1; ++n) {
        int b = batch[n];
        if (b != cur) {
            atomicMax((int*)&pooled[cur * 128 + j], __float_as_int(m));
            cur = b; m = 0.0f;
        }
        m = fmaxf(m, h[(size_t)n * 128 + j]);
    }
    atomicMax((int*)&pooled[cur * 128 + j], __float_as_int(m));
}

// ---------------- head ----------------
__global__ void head_kernel(const float* __restrict__ pooled,
                            const float* __restrict__ w1, const float* __restrict__ b1,
                            const float* __restrict__ w2, const float* __restrict__ b2,
                            float* __restrict__ out)
{
    __shared__ float t[NGRAPH][HID];
    int tid = threadIdx.x;
    for (int o = tid; o < NGRAPH * HID; o += blockDim.x) {
        int r = o >> 7, c = o & 127;
        float s = b1[c];
        #pragma unroll 8
        for (int k = 0; k < 128; ++k) s = fmaf(pooled[r * 128 + k], w1[k * 128 + c], s);
        t[r][c] = s;
    }
    __syncthreads();
    if (tid < NGRAPH) {
        float z0 = b2[0], z1 = b2[1];
        #pragma unroll 8
        for (int k = 0; k < 128; ++k) {
            float v = t[tid][k];
            z0 = fmaf(v, w2[k * 2 + 0], z0);
            z1 = fmaf(v, w2[k * 2 + 1], z1);
        }
        float m = fmaxf(z0, z1);
        float lse = m + logf(expf(z0 - m) + expf(z1 - m));
        out[tid * 2 + 0] = z0 - lse;
        out[tid * 2 + 1] = z1 - lse;
    }
}

// ---------------- launch ----------------
extern "C" void kernel_launch(void* const* d_in, const int* in_sizes, int n_in,
                              void* d_out, int out_size)
{
    const float* x      = (const float*)d_in[0];
    const int*   ei     = (const int*)  d_in[1];
    const int*   batch  = (const int*)  d_in[2];
    const float* lin_w0 = (const float*)d_in[3];
    const float* lin_b0 = (const float*)d_in[4];
    const float* agg_w0 = (const float*)d_in[5];
    const float* agg_b0 = (const float*)d_in[6];
    const float* lin_w1 = (const float*)d_in[7];
    const float* lin_b1 = (const float*)d_in[8];
    const float* agg_w1 = (const float*)d_in[9];
    const float* agg_b1 = (const float*)d_in[10];
    const float* mp_w1  = (const float*)d_in[11];
    const float* mp_b1  = (const float*)d_in[12];
    const float* mp_w2  = (const float*)d_in[13];
    const float* mp_b2  = (const float*)d_in[14];
    float* out = (float*)d_out;

    const int N = in_sizes[0] / HID;
    const int E = in_sizes[1] / 2;
    const int* src = ei;
    const int* dst = ei + E;

    void *p;
    float *y, *pooled;
    int *cnt, *off, *fill, *srcs;
    __nv_bfloat16 *xhi, *xlo, *yhi, *ylo, *h0hi, *h0lo, *ahi, *alo, *wthi, *wtlo;
    cudaGetSymbolAddress(&p, g_y);      y      = (float*)p;
    cudaGetSymbolAddress(&p, g_pooled); pooled = (float*)p;
    cudaGetSymbolAddress(&p, g_cnt);    cnt    = (int*)p;
    cudaGetSymbolAddress(&p, g_off);    off    = (int*)p;
    cudaGetSymbolAddress(&p, g_fill);   fill   = (int*)p;
    cudaGetSymbolAddress(&p, g_srcs);   srcs   = (int*)p;
    cudaGetSymbolAddress(&p, g_xhi);    xhi    = (__nv_bfloat16*)p;
    cudaGetSymbolAddress(&p, g_xlo);    xlo    = (__nv_bfloat16*)p;
    cudaGetSymbolAddress(&p, g_yhi);    yhi    = (__nv_bfloat16*)p;
    cudaGetSymbolAddress(&p, g_ylo);    ylo    = (__nv_bfloat16*)p;
    cudaGetSymbolAddress(&p, g_h0hi);   h0hi   = (__nv_bfloat16*)p;
    cudaGetSymbolAddress(&p, g_h0lo);   h0lo   = (__nv_bfloat16*)p;
    cudaGetSymbolAddress(&p, g_agghi);  ahi    = (__nv_bfloat16*)p;
    cudaGetSymbolAddress(&p, g_agglo);  alo    = (__nv_bfloat16*)p;
    cudaGetSymbolAddress(&p, g_wthi);   wthi   = (__nv_bfloat16*)p;
    cudaGetSymbolAddress(&p, g_wtlo);   wtlo   = (__nv_bfloat16*)p;

    cudaFuncSetAttribute(gemm_mma, cudaFuncAttributeMaxDynamicSharedMemorySize, SMEM_GEMM);

    const int gridM = (N + 127) / 128;
    const int zeroN = (N + 1 > NGRAPH * HID) ? (N + 1) : NGRAPH * HID;

    // launch 1-3: converts + zero
    {
        dim3 g((128 * 256 + 255) / 256, 4);
        wconvert_all<<<g, 256>>>(lin_w0, agg_w0, lin_w1, agg_w1, wthi, wtlo);
    }
    xconvert_kernel<<<(N * 32 + 255) / 256, 256>>>(x, xhi, xlo, N * 32);
    zero_kernel<<<(zeroN + 255) / 256, 256>>>(cnt, pooled, N + 1, NGRAPH * HID);

    // launch 4: first GEMM (ncu capture slot)
    gemm_mma<<<gridM, 256, SMEM_GEMM>>>(xhi, xlo, nullptr, nullptr,
                                        wthi, wtlo, 128, lin_b0,
                                        nullptr, yhi, ylo, N, 0);

    // launches 5-7: CSR build
    hist_kernel<<<(E + 255) / 256, 256>>>(dst, cnt, E);
    scan_kernel<<<1, 1024>>>(cnt, off, fill, N);
    fill_kernel<<<(E + 255) / 256, 256>>>(src, dst, fill, srcs, E);

    // layer 0
    agg_kernel<<<(N + 7) / 8, 256>>>(yhi, ylo, ahi, alo, off, srcs, N);
    gemm_mma<<<gridM, 256, SMEM_GEMM>>>(ahi, alo, xhi, xlo,
                                        wthi + 16384, wtlo + 16384, 256, agg_b0,
                                        nullptr, h0hi, h0lo, N, 1);
    // layer 1
    gemm_mma<<<gridM, 256, SMEM_GEMM>>>(h0hi, h0lo, nullptr, nullptr,
                                        wthi + 49152, wtlo + 49152, 128, lin_b1,
                                        nullptr, yhi, ylo, N, 0);
    agg_kernel<<<(N + 7) / 8, 256>>>(yhi, ylo, ahi, alo, off, srcs, N);
    gemm_mma<<<gridM, 256, SMEM_GEMM>>>(ahi, alo, h0hi, h0lo,
                                        wthi + 65536, wtlo + 65536, 256, agg_b1,
                                        y, nullptr, nullptr, N, 1);

    // pool + head
    pool_kernel<<<(N + POOL_CHUNK - 1) / POOL_CHUNK, 128>>>(y, batch, pooled, N);
    head_kernel<<<1, 256>>>(pooled, mp_w1, mp_b1, mp_w2, mp_b2, out);
}

// round 8
// speedup vs baseline: 1.1025x; 1.0383x over previous
#include <cuda_runtime.h>
#include <cuda_bf16.h>
#include <math.h>

#define MAXN 50000
#define MAXE 600000
#define HID 128
#define NGRAPH 64
#define GEMM_GRID 296   // 2 CTAs/SM x 148 SMs, persistent tile loop

// ---------------- scratch (static device globals) ----------------
__device__ __nv_bfloat16 g_xhi[(size_t)MAXN * HID];
__device__ __nv_bfloat16 g_xlo[(size_t)MAXN * HID];
__device__ __nv_bfloat16 g_yhi[(size_t)MAXN * HID];
__device__ __nv_bfloat16 g_ylo[(size_t)MAXN * HID];
__device__ __nv_bfloat16 g_h0hi[(size_t)MAXN * HID];
__device__ __nv_bfloat16 g_h0lo[(size_t)MAXN * HID];
__device__ __nv_bfloat16 g_agghi[(size_t)MAXN * HID];
__device__ __nv_bfloat16 g_agglo[(size_t)MAXN * HID];
__device__ int   g_cnt[MAXN + 1];
__device__ int   g_off[MAXN + 1];
__device__ int   g_fill[MAXN];
__device__ int   g_srcs[MAXE];
__device__ float g_pooled[NGRAPH * HID];
__device__ __nv_bfloat16 g_wthi[128 * 768];
__device__ __nv_bfloat16 g_wtlo[128 * 768];

// ---------------- tiny helpers ----------------
__device__ __forceinline__ void cpa16(unsigned dst, const void* src, int pbytes) {
    asm volatile("cp.async.cg.shared.global [%0], [%1], 16, %2;\n"
                 :: "r"(dst), "l"(src), "r"(pbytes));
}
__device__ __forceinline__ void cpa_commit() { asm volatile("cp.async.commit_group;\n"); }
__device__ __forceinline__ void cpa_wait0()  { asm volatile("cp.async.wait_group 0;\n"); }

__device__ __forceinline__ void mma16816(float c[4], const unsigned a[4], const unsigned* b) {
    asm volatile(
        "mma.sync.aligned.m16n8k16.row.col.f32.bf16.bf16.f32 "
        "{%0,%1,%2,%3},{%4,%5,%6,%7},{%8,%9},{%0,%1,%2,%3};"
        : "+f"(c[0]), "+f"(c[1]), "+f"(c[2]), "+f"(c[3])
        : "r"(a[0]), "r"(a[1]), "r"(a[2]), "r"(a[3]), "r"(b[0]), "r"(b[1]));
}
__device__ __forceinline__ void ldsm_x4(unsigned r[4], unsigned addr) {
    asm volatile("ldmatrix.sync.aligned.m8n8.x4.shared.b16 {%0,%1,%2,%3}, [%4];"
                 : "=r"(r[0]), "=r"(r[1]), "=r"(r[2]), "=r"(r[3]) : "r"(addr));
}

// ---------------- conversion kernels ----------------
__global__ void wconvert_all(const float* __restrict__ w0, const float* __restrict__ wa0,
                             const float* __restrict__ w1, const float* __restrict__ wa1,
                             __nv_bfloat16* __restrict__ hi, __nv_bfloat16* __restrict__ lo)
{
    const int r = blockIdx.y;
    const int K   = (r & 1) ? 256 : 128;
    const int off = (r == 0) ? 0 : (r == 1) ? 16384 : (r == 2) ? 49152 : 65536;
    const float* W = (r == 0) ? w0 : (r == 1) ? wa0 : (r == 2) ? w1 : wa1;
    int idx = blockIdx.x * blockDim.x + threadIdx.x;
    if (idx >= 128 * K) return;
    int n = idx / K, k = idx % K;
    float v = W[(size_t)k * 128 + n];
    __nv_bfloat16 h = __float2bfloat16(v);
    hi[off + idx] = h;
    lo[off + idx] = __float2bfloat16(v - __bfloat162float(h));
}

__global__ void xconvert_kernel(const float* __restrict__ x,
                                __nv_bfloat16* __restrict__ hi,
                                __nv_bfloat16* __restrict__ lo, int total4)
{
    int i = blockIdx.x * blockDim.x + threadIdx.x;
    if (i >= total4) return;
    float4 v = *(const float4*)(x + (size_t)i * 4);
    __nv_bfloat16 h0 = __float2bfloat16(v.x), h1 = __float2bfloat16(v.y);
    __nv_bfloat16 h2 = __float2bfloat16(v.z), h3 = __float2bfloat16(v.w);
    __nv_bfloat162 hp0(h0, h1), hp1(h2, h3);
    __nv_bfloat162 lp0(__float2bfloat16(v.x - __bfloat162float(h0)),
                       __float2bfloat16(v.y - __bfloat162float(h1)));
    __nv_bfloat162 lp1(__float2bfloat16(v.z - __bfloat162float(h2)),
                       __float2bfloat16(v.w - __bfloat162float(h3)));
    *(__nv_bfloat162*)(hi + (size_t)i * 4)     = hp0;
    *(__nv_bfloat162*)(hi + (size_t)i * 4 + 2) = hp1;
    *(__nv_bfloat162*)(lo + (size_t)i * 4)     = lp0;
    *(__nv_bfloat162*)(lo + (size_t)i * 4 + 2) = lp1;
}

// ---------------- CSR build ----------------
__global__ void zero_kernel(int* cnt, float* pooled, int ncnt, int npool) {
    int i = blockIdx.x * blockDim.x + threadIdx.x;
    if (i < ncnt)  cnt[i] = 0;
    if (i < npool) pooled[i] = 0.0f;
}
__global__ void hist_kernel(const int* __restrict__ dst, int* __restrict__ cnt, int E) {
    int e = blockIdx.x * blockDim.x + threadIdx.x;
    if (e < E) atomicAdd(&cnt[dst[e]], 1);
}
__global__ void scan_kernel(const int* __restrict__ cnt, int* __restrict__ off,
                            int* __restrict__ fill, int N) {
    __shared__ int warpsum[32];
    __shared__ int s_carry;
    const int tid = threadIdx.x;
    if (tid == 0) s_carry = 0;
    __syncthreads();
    for (int base = 0; base < N; base += 1024) {
        int i = base + tid;
        int v = (i < N) ? cnt[i] : 0;
        int x = v;
        #pragma unroll
        for (int d = 1; d < 32; d <<= 1) {
            int t = __shfl_up_sync(0xffffffffu, x, d);
            if ((tid & 31) >= d) x += t;
        }
        if ((tid & 31) == 31) warpsum[tid >> 5] = x;
        __syncthreads();
        if (tid < 32) {
            int w = warpsum[tid];
            #pragma unroll
            for (int d = 1; d < 32; d <<= 1) {
                int t = __shfl_up_sync(0xffffffffu, w, d);
                if (tid >= d) w += t;
            }
            warpsum[tid] = w;
        }
        __syncthreads();
        int warpOff = (tid >= 32) ? warpsum[(tid >> 5) - 1] : 0;
        int excl = s_carry + warpOff + x - v;
        if (i < N) { off[i] = excl; fill[i] = excl; }
        __syncthreads();
        if (tid == 0) s_carry += warpsum[31];
        __syncthreads();
    }
    if (tid == 0) off[N] = s_carry;
}
__global__ void fill_kernel(const int* __restrict__ src, const int* __restrict__ dst,
                            int* __restrict__ fill, int* __restrict__ srcs, int E) {
    int e = blockIdx.x * blockDim.x + threadIdx.x;
    if (e < E) {
        int p = atomicAdd(&fill[dst[e]], 1);
        srcs[p] = src[e];
    }
}

// ---------------- GEMM: persistent, 2-stage cp.async, ldmatrix, optional fused pool ----------------
#define APAD 40
#define STG_ELEMS (4 * 128 * APAD)
#define POOL_SPAN 4
#define SMEM_GEMM (2 * STG_ELEMS * 2 + 1024 + POOL_SPAN * 128 * 4)

__device__ __forceinline__ void stage_chunk(
    const __nv_bfloat16* __restrict__ A1hi, const __nv_bfloat16* __restrict__ A1lo,
    const __nv_bfloat16* __restrict__ A2hi, const __nv_bfloat16* __restrict__ A2lo,
    const __nv_bfloat16* __restrict__ wthi, const __nv_bfloat16* __restrict__ wtlo,
    int Ktot, unsigned sbase, int kg, int rowBase, int M, int tid)
{
    const __nv_bfloat16* Ahi = (kg < 128) ? A1hi : A2hi;
    const __nv_bfloat16* Alo = (kg < 128) ? A1lo : A2lo;
    const int kk = (kg < 128) ? kg : kg - 128;
    #pragma unroll
    for (int p = 0; p < 2; ++p) {
        int idx = p * 256 + tid;
        int row = idx >> 2, seg = idx & 3;
        int g = rowBase + row;
        int pb = (g < M) ? 16 : 0;
        int gc = (g < M) ? g : 0;
        size_t so = (size_t)gc * 128 + kk + seg * 8;
        unsigned d = sbase + (row * APAD + seg * 8) * 2;
        cpa16(d,                  Ahi + so, pb);
        cpa16(d + 128 * APAD * 2, Alo + so, pb);
    }
    #pragma unroll
    for (int p = 0; p < 2; ++p) {
        int idx = p * 256 + tid;
        int n = idx >> 2, seg = idx & 3;
        size_t so = (size_t)n * Ktot + kg + seg * 8;
        unsigned d = sbase + (2 * 128 * APAD + n * APAD + seg * 8) * 2;
        cpa16(d,                  wthi + so, 16);
        cpa16(d + 128 * APAD * 2, wtlo + so, 16);
    }
}

__global__ __launch_bounds__(256, 2)
void gemm_mma(const __nv_bfloat16* __restrict__ A1hi, const __nv_bfloat16* __restrict__ A1lo,
              const __nv_bfloat16* __restrict__ A2hi, const __nv_bfloat16* __restrict__ A2lo,
              const __nv_bfloat16* __restrict__ wthi, const __nv_bfloat16* __restrict__ wtlo,
              int Ktot, const float* __restrict__ bias,
              __nv_bfloat16* __restrict__ Chi, __nv_bfloat16* __restrict__ Clo,
              const int* __restrict__ batch, float* __restrict__ pooled,
              int M, int doNorm, int nTiles)
{
    extern __shared__ __align__(16) __nv_bfloat16 smem[];
    float* rowss = (float*)(smem + 2 * STG_ELEMS);
    float* spool = rowss + 256;           // POOL_SPAN*128 floats
    const unsigned sb = (unsigned)__cvta_generic_to_shared(smem);

    const int tid = threadIdx.x;
    const int wid = tid >> 5, lane = tid & 31;
    const int wm = wid & 3, wn = wid >> 2;
    const int g4 = lane >> 2, q = lane & 3;

    const int aRow = wm * 32 + (lane & 15);
    const int aCol = (lane & 16) ? 8 : 0;
    const unsigned aAddr0 = sb + (unsigned)(aRow * APAD + aCol) * 2;
    const int bRow = wn * 64 + (lane & 7) + ((lane & 16) ? 8 : 0);
    const int bCol = (lane & 8) ? 8 : 0;
    const unsigned bAddr0 = sb + (unsigned)(2 * 128 * APAD + bRow * APAD + bCol) * 2;
    const unsigned LOOFF = 128 * APAD * 2;
    const unsigned I16   = 16 * APAD * 2;
    const int nChunks = Ktot / 32;   // 4 or 8 (even)

    for (int tile = blockIdx.x; tile < nTiles; tile += gridDim.x) {
        const int rowBase = tile * 128;

        float acc[2][8][4];
        #pragma unroll
        for (int i = 0; i < 2; ++i)
            #pragma unroll
            for (int j = 0; j < 8; ++j)
                #pragma unroll
                for (int v = 0; v < 4; ++v) acc[i][j][v] = 0.0f;

        stage_chunk(A1hi, A1lo, A2hi, A2lo, wthi, wtlo, Ktot, sb, 0, rowBase, M, tid);
        cpa_commit();

        for (int kc = 0; kc < nChunks; ++kc) {
            cpa_wait0();
            __syncthreads();
            if (kc + 1 < nChunks) {
                stage_chunk(A1hi, A1lo, A2hi, A2lo, wthi, wtlo, Ktot,
                            sb + ((kc + 1) & 1) * STG_ELEMS * 2, (kc + 1) * 32, rowBase, M, tid);
                cpa_commit();
            }
            const unsigned stoff = ((unsigned)(kc & 1)) * STG_ELEMS * 2;
            #pragma unroll
            for (int k16 = 0; k16 < 2; ++k16) {
                const unsigned kb = (unsigned)k16 * 32;
                unsigned ah0[4], ah1[4], al0[4], al1[4];
                ldsm_x4(ah0, aAddr0 + stoff + kb);
                ldsm_x4(ah1, aAddr0 + stoff + kb + I16);
                ldsm_x4(al0, aAddr0 + stoff + kb + LOOFF);
                ldsm_x4(al1, aAddr0 + stoff + kb + LOOFF + I16);
                unsigned bh[4][4], bl[4][4];
                #pragma unroll
                for (int jj = 0; jj < 4; ++jj) {
                    unsigned ba = bAddr0 + stoff + kb + (unsigned)jj * I16;
                    ldsm_x4(bh[jj], ba);
                    ldsm_x4(bl[jj], ba + LOOFF);
                }
                #pragma unroll
                for (int jj = 0; jj < 4; ++jj) {
                    mma16816(acc[0][2 * jj],     ah0, &bh[jj][0]);
                    mma16816(acc[1][2 * jj],     ah1, &bh[jj][0]);
                    mma16816(acc[0][2 * jj + 1], ah0, &bh[jj][2]);
                    mma16816(acc[1][2 * jj + 1], ah1, &bh[jj][2]);
                }
                #pragma unroll
                for (int jj = 0; jj < 4; ++jj) {
                    mma16816(acc[0][2 * jj],     ah0, &bl[jj][0]);
                    mma16816(acc[1][2 * jj],     ah1, &bl[jj][0]);
                    mma16816(acc[0][2 * jj + 1], ah0, &bl[jj][2]);
                    mma16816(acc[1][2 * jj + 1], ah1, &bl[jj][2]);
                }
                #pragma unroll
                for (int jj = 0; jj < 4; ++jj) {
                    mma16816(acc[0][2 * jj],     al0, &bh[jj][0]);
                    mma16816(acc[1][2 * jj],     al1, &bh[jj][0]);
                    mma16816(acc[0][2 * jj + 1], al0, &bh[jj][2]);
                    mma16816(acc[1][2 * jj + 1], al1, &bh[jj][2]);
                }
            }
        }

        // ---- epilogue: bias + relu (+ L2 norm) ----
        #pragma unroll
        for (int j = 0; j < 8; ++j) {
            int col = wn * 64 + j * 8 + q * 2;
            float2 b = *(const float2*)(bias + col);
            #pragma unroll
            for (int i = 0; i < 2; ++i) {
                acc[i][j][0] = fmaxf(acc[i][j][0] + b.x, 0.0f);
                acc[i][j][1] = fmaxf(acc[i][j][1] + b.y, 0.0f);
                acc[i][j][2] = fmaxf(acc[i][j][2] + b.x, 0.0f);
                acc[i][j][3] = fmaxf(acc[i][j][3] + b.y, 0.0f);
            }
        }
        if (doNorm) {
            __syncthreads();
            #pragma unroll
            for (int i = 0; i < 2; ++i) {
                int r = wm * 32 + i * 16 + g4;
                float ssLo = 0.f, ssHi = 0.f;
                #pragma unroll
                for (int j = 0; j < 8; ++j) {
                    ssLo += acc[i][j][0] * acc[i][j][0] + acc[i][j][1] * acc[i][j][1];
                    ssHi += acc[i][j][2] * acc[i][j][2] + acc[i][j][3] * acc[i][j][3];
                }
                ssLo += __shfl_xor_sync(0xffffffffu, ssLo, 1);
                ssLo += __shfl_xor_sync(0xffffffffu, ssLo, 2);
                ssHi += __shfl_xor_sync(0xffffffffu, ssHi, 1);
                ssHi += __shfl_xor_sync(0xffffffffu, ssHi, 2);
                if (q == 0) { rowss[r * 2 + wn] = ssLo; rowss[(r + 8) * 2 + wn] = ssHi; }
            }
            __syncthreads();
            #pragma unroll
            for (int i = 0; i < 2; ++i) {
                int r = wm * 32 + i * 16 + g4;
                float invLo = 1.0f / fmaxf(sqrtf(rowss[r * 2] + rowss[r * 2 + 1]), 1e-12f);
                float invHi = 1.0f / fmaxf(sqrtf(rowss[(r + 8) * 2] + rowss[(r + 8) * 2 + 1]), 1e-12f);
                #pragma unroll
                for (int j = 0; j < 8; ++j) {
                    acc[i][j][0] *= invLo; acc[i][j][1] *= invLo;
                    acc[i][j][2] *= invHi; acc[i][j][3] *= invHi;
                }
            }
        }

        if (pooled) {
            // CTA-level smem pool reduction, then spread global atomics.
            for (int s = tid; s < POOL_SPAN * 128; s += 256) spool[s] = 0.0f;
            __syncthreads();
            const int gLo = batch[rowBase];   // batch sorted; tile exists -> valid
            #pragma unroll
            for (int i = 0; i < 2; ++i) {
                int r0 = rowBase + wm * 32 + i * 16 + g4;
                int r1 = r0 + 8;
                int dg0 = (r0 < M) ? (batch[r0] - gLo) : -1;
                int dg1 = (r1 < M) ? (batch[r1] - gLo) : -1;
                #pragma unroll
                for (int j = 0; j < 8; ++j) {
                    int col = wn * 64 + j * 8 + q * 2;
                    if (dg0 >= 0) {
                        if (dg0 < POOL_SPAN) {
                            atomicMax((int*)&spool[dg0 * 128 + col],     __float_as_int(acc[i][j][0]));
                            atomicMax((int*)&spool[dg0 * 128 + col + 1], __float_as_int(acc[i][j][1]));
                        } else {
                            atomicMax((int*)&pooled[(gLo + dg0) * 128 + col],     __float_as_int(acc[i][j][0]));
                            atomicMax((int*)&pooled[(gLo + dg0) * 128 + col + 1], __float_as_int(acc[i][j][1]));
                        }
                    }
                    if (dg1 >= 0) {
                        if (dg1 < POOL_SPAN) {
                            atomicMax((int*)&spool[dg1 * 128 + col],     __float_as_int(acc[i][j][2]));
                            atomicMax((int*)&spool[dg1 * 128 + col + 1], __float_as_int(acc[i][j][3]));
                        } else {
                            atomicMax((int*)&pooled[(gLo + dg1) * 128 + col],     __float_as_int(acc[i][j][2]));
                            atomicMax((int*)&pooled[(gLo + dg1) * 128 + col + 1], __float_as_int(acc[i][j][3]));
                        }
                    }
                }
            }
            __syncthreads();
            for (int s = tid; s < POOL_SPAN * 128; s += 256) {
                float v = spool[s];
                int gIdx = gLo + (s >> 7);
                if (v > 0.0f && gIdx < NGRAPH)
                    atomicMax((int*)&pooled[gIdx * 128 + (s & 127)], __float_as_int(v));
            }
            __syncthreads();
        } else {
            #pragma unroll
            for (int i = 0; i < 2; ++i) {
                int r0 = rowBase + wm * 32 + i * 16 + g4;
                #pragma unroll
                for (int j = 0; j < 8; ++j) {
                    int col = wn * 64 + j * 8 + q * 2;
                    __nv_bfloat16 h0 = __float2bfloat16(acc[i][j][0]);
                    __nv_bfloat16 h1 = __float2bfloat16(acc[i][j][1]);
                    __nv_bfloat16 h2 = __float2bfloat16(acc[i][j][2]);
                    __nv_bfloat16 h3 = __float2bfloat16(acc[i][j][3]);
                    __nv_bfloat162 lp0(__float2bfloat16(acc[i][j][0] - __bfloat162float(h0)),
                                       __float2bfloat16(acc[i][j][1] - __bfloat162float(h1)));
                    __nv_bfloat162 lp1(__float2bfloat16(acc[i][j][2] - __bfloat162float(h2)),
                                       __float2bfloat16(acc[i][j][3] - __bfloat162float(h3)));
                    if (r0 < M) {
                        *(__nv_bfloat162*)(Chi + (size_t)r0 * 128 + col) = __nv_bfloat162(h0, h1);
                        *(__nv_bfloat162*)(Clo + (size_t)r0 * 128 + col) = lp0;
                    }
                    if (r0 + 8 < M) {
                        *(__nv_bfloat162*)(Chi + (size_t)(r0 + 8) * 128 + col) = __nv_bfloat162(h2, h3);
                        *(__nv_bfloat162*)(Clo + (size_t)(r0 + 8) * 128 + col) = lp1;
                    }
                }
            }
            __syncthreads();   // protect smem reuse across persistent tiles
        }
    }
}

// ---------------- CSR mean aggregation (bf16 hi/lo): lane handles 4 features ----------------
__global__ void agg_kernel(const __nv_bfloat16* __restrict__ yhi,
                           const __nv_bfloat16* __restrict__ ylo,
                           __nv_bfloat16* __restrict__ ahi,
                           __nv_bfloat16* __restrict__ alo,
                           const int* __restrict__ off, const int* __restrict__ srcs,
                           int N)
{
    int w = (blockIdx.x * blockDim.x + threadIdx.x) >> 5;
    int lane = threadIdx.x & 31;
    if (w >= N) return;
    int s0 = off[w], s1 = off[w + 1];
    float acc0 = 0.f, acc1 = 0.f, acc2 = 0.f, acc3 = 0.f;
    int i = s0;
    for (; i + 1 < s1; i += 2) {
        int sA = __ldg(&srcs[i]);
        int sB = __ldg(&srcs[i + 1]);
        uint2 hA = *(const uint2*)(yhi + (size_t)sA * 128 + lane * 4);
        uint2 lA = *(const uint2*)(ylo + (size_t)sA * 128 + lane * 4);
        uint2 hB = *(const uint2*)(yhi + (size_t)sB * 128 + lane * 4);
        uint2 lB = *(const uint2*)(ylo + (size_t)sB * 128 + lane * 4);
        float2 a = __bfloat1622float2(*(const __nv_bfloat162*)&hA.x);
        float2 b = __bfloat1622float2(*(const __nv_bfloat162*)&hA.y);
        float2 c = __bfloat1622float2(*(const __nv_bfloat162*)&lA.x);
        float2 d = __bfloat1622float2(*(const __nv_bfloat162*)&lA.y);
        acc0 += a.x + c.x; acc1 += a.y + c.y; acc2 += b.x + d.x; acc3 += b.y + d.y;
        a = __bfloat1622float2(*(const __nv_bfloat162*)&hB.x);
        b = __bfloat1622float2(*(const __nv_bfloat162*)&hB.y);
        c = __bfloat1622float2(*(const __nv_bfloat162*)&lB.x);
        d = __bfloat1622float2(*(const __nv_bfloat162*)&lB.y);
        acc0 += a.x + c.x; acc1 += a.y + c.y; acc2 += b.x + d.x; acc3 += b.y + d.y;
    }
    if (i < s1) {
        int sA = __ldg(&srcs[i]);
        uint2 hA = *(const uint2*)(yhi + (size_t)sA * 128 + lane * 4);
        uint2 lA = *(const uint2*)(ylo + (size_t)sA * 128 + lane * 4);
        float2 a = __bfloat1622float2(*(const __nv_bfloat162*)&hA.x);
        float2 b = __bfloat1622float2(*(const __nv_bfloat162*)&hA.y);
        float2 c = __bfloat1622float2(*(const __nv_bfloat162*)&lA.x);
        float2 d = __bfloat1622float2(*(const __nv_bfloat162*)&lA.y);
        acc0 += a.x + c.x; acc1 += a.y + c.y; acc2 += b.x + d.x; acc3 += b.y + d.y;
    }
    float inv = 1.0f / fmaxf((float)(s1 - s0), 1.0f);
    acc0 *= inv; acc1 *= inv; acc2 *= inv; acc3 *= inv;
    __nv_bfloat16 h0 = __float2bfloat16(acc0), h1 = __float2bfloat16(acc1);
    __nv_bfloat16 h2 = __float2bfloat16(acc2), h3 = __float2bfloat16(acc3);
    __nv_bfloat162 hp0(h0, h1), hp1(h2, h3);
    __nv_bfloat162 lp0(__float2bfloat16(acc0 - __bfloat162float(h0)),
                       __float2bfloat16(acc1 - __bfloat162float(h1)));
    __nv_bfloat162 lp1(__float2bfloat16(acc2 - __bfloat162float(h2)),
                       __float2bfloat16(acc3 - __bfloat162float(h3)));
    *(__nv_bfloat162*)(ahi + (size_t)w * 128 + lane * 4)     = hp0;
    *(__nv_bfloat162*)(ahi + (size_t)w * 128 + lane * 4 + 2) = hp1;
    *(__nv_bfloat162*)(alo + (size_t)w * 128 + lane * 4)     = lp0;
    *(__nv_bfloat162*)(alo + (size_t)w * 128 + lane * 4 + 2) = lp1;
}

// ---------------- head ----------------
__global__ void head_kernel(const float* __restrict__ pooled,
                            const float* __restrict__ w1, const float* __restrict__ b1,
                            const float* __restrict__ w2, const float* __restrict__ b2,
                            float* __restrict__ out)
{
    __shared__ float t[NGRAPH][HID];
    int tid = threadIdx.x;
    for (int o = tid; o < NGRAPH * HID; o += blockDim.x) {
        int r = o >> 7, c = o & 127;
        float s = b1[c];
        #pragma unroll 8
        for (int k = 0; k < 128; ++k) s = fmaf(pooled[r * 128 + k], w1[k * 128 + c], s);
        t[r][c] = s;
    }
    __syncthreads();
    if (tid < NGRAPH) {
        float z0 = b2[0], z1 = b2[1];
        #pragma unroll 8
        for (int k = 0; k < 128; ++k) {
            float v = t[tid][k];
            z0 = fmaf(v, w2[k * 2 + 0], z0);
            z1 = fmaf(v, w2[k * 2 + 1], z1);
        }
        float m = fmaxf(z0, z1);
        float lse = m + logf(expf(z0 - m) + expf(z1 - m));
        out[tid * 2 + 0] = z0 - lse;
        out[tid * 2 + 1] = z1 - lse;
    }
}

// ---------------- launch ----------------
extern "C" void kernel_launch(void* const* d_in, const int* in_sizes, int n_in,
                              void* d_out, int out_size)
{
    const float* x      = (const float*)d_in[0];
    const int*   ei     = (const int*)  d_in[1];
    const int*   batch  = (const int*)  d_in[2];
    const float* lin_w0 = (const float*)d_in[3];
    const float* lin_b0 = (const float*)d_in[4];
    const float* agg_w0 = (const float*)d_in[5];
    const float* agg_b0 = (const float*)d_in[6];
    const float* lin_w1 = (const float*)d_in[7];
    const float* lin_b1 = (const float*)d_in[8];
    const float* agg_w1 = (const float*)d_in[9];
    const float* agg_b1 = (const float*)d_in[10];
    const float* mp_w1  = (const float*)d_in[11];
    const float* mp_b1  = (const float*)d_in[12];
    const float* mp_w2  = (const float*)d_in[13];
    const float* mp_b2  = (const float*)d_in[14];
    float* out = (float*)d_out;

    const int N = in_sizes[0] / HID;
    const int E = in_sizes[1] / 2;
    const int* src = ei;
    const int* dst = ei + E;

    void *p;
    float *pooled;
    int *cnt, *off, *fill, *srcs;
    __nv_bfloat16 *xhi, *xlo, *yhi, *ylo, *h0hi, *h0lo, *ahi, *alo, *wthi, *wtlo;
    cudaGetSymbolAddress(&p, g_pooled); pooled = (float*)p;
    cudaGetSymbolAddress(&p, g_cnt);    cnt    = (int*)p;
    cudaGetSymbolAddress(&p, g_off);    off    = (int*)p;
    cudaGetSymbolAddress(&p, g_fill);   fill   = (int*)p;
    cudaGetSymbolAddress(&p, g_srcs);   srcs   = (int*)p;
    cudaGetSymbolAddress(&p, g_xhi);    xhi    = (__nv_bfloat16*)p;
    cudaGetSymbolAddress(&p, g_xlo);    xlo    = (__nv_bfloat16*)p;
    cudaGetSymbolAddress(&p, g_yhi);    yhi    = (__nv_bfloat16*)p;
    cudaGetSymbolAddress(&p, g_ylo);    ylo    = (__nv_bfloat16*)p;
    cudaGetSymbolAddress(&p, g_h0hi);   h0hi   = (__nv_bfloat16*)p;
    cudaGetSymbolAddress(&p, g_h0lo);   h0lo   = (__nv_bfloat16*)p;
    cudaGetSymbolAddress(&p, g_agghi);  ahi    = (__nv_bfloat16*)p;
    cudaGetSymbolAddress(&p, g_agglo);  alo    = (__nv_bfloat16*)p;
    cudaGetSymbolAddress(&p, g_wthi);   wthi   = (__nv_bfloat16*)p;
    cudaGetSymbolAddress(&p, g_wtlo);   wtlo   = (__nv_bfloat16*)p;

    cudaFuncSetAttribute(gemm_mma, cudaFuncAttributeMaxDynamicSharedMemorySize, SMEM_GEMM);

    const int nTiles = (N + 127) / 128;
    const int gridG  = (nTiles < GEMM_GRID) ? nTiles : GEMM_GRID;
    const int zeroN = (N + 1 > NGRAPH * HID) ? (N + 1) : NGRAPH * HID;

    // launch 1-3: converts + zero
    {
        dim3 g((128 * 256 + 255) / 256, 4);
        wconvert_all<<<g, 256>>>(lin_w0, agg_w0, lin_w1, agg_w1, wthi, wtlo);
    }
    xconvert_kernel<<<(N * 32 + 255) / 256, 256>>>(x, xhi, xlo, N * 32);
    zero_kernel<<<(zeroN + 255) / 256, 256>>>(cnt, pooled, N + 1, NGRAPH * HID);

    // launch 4: first GEMM (ncu capture slot)
    gemm_mma<<<gridG, 256, SMEM_GEMM>>>(xhi, xlo, nullptr, nullptr,
                                        wthi, wtlo, 128, lin_b0,
                                        yhi, ylo, nullptr, nullptr, N, 0, nTiles);

    // launches 5-7: CSR build
    hist_kernel<<<(E + 255) / 256, 256>>>(dst, cnt, E);
    scan_kernel<<<1, 1024>>>(cnt, off, fill, N);
    fill_kernel<<<(E + 255) / 256, 256>>>(src, dst, fill, srcs, E);

    // layer 0
    agg_kernel<<<(N + 7) / 8, 256>>>(yhi, ylo, ahi, alo, off, srcs, N);
    gemm_mma<<<gridG, 256, SMEM_GEMM>>>(ahi, alo, xhi, xlo,
                                        wthi + 16384, wtlo + 16384, 256, agg_b0,
                                        h0hi, h0lo, nullptr, nullptr, N, 1, nTiles);
    // layer 1
    gemm_mma<<<gridG, 256, SMEM_GEMM>>>(h0hi, h0lo, nullptr, nullptr,
                                        wthi + 49152, wtlo + 49152, 128, lin_b1,
                                        yhi, ylo, nullptr, nullptr, N, 0, nTiles);
    agg_kernel<<<(N + 7) / 8, 256>>>(yhi, ylo, ahi, alo, off, srcs, N);
    // final GEMM: norm + fused smem-reduced max pool
    gemm_mma<<<gridG, 256, SMEM_GEMM>>>(ahi, alo, h0hi, h0lo,
                                        wthi + 65536, wtlo + 65536, 256, agg_b1,
                                        nullptr, nullptr, batch, pooled, N, 1, nTiles);

    // head
    head_kernel<<<1, 256>>>(pooled, mp_w1, mp_b1, mp_w2, mp_b2, out);
}